// round 1
// baseline (speedup 1.0000x reference)
#include <cuda_runtime.h>
#include <math.h>
#include <stdint.h>

// Problem constants
#define B_ 2
#define N_ 8192
#define C_ 256
#define H_ 8
#define CH_ 32
#define M_ 32
#define HID_ 512
#define TAB_ 3025
#define NTOK (B_*N_)   // 16384

// ---------------- scratch (device globals; no allocation allowed) ------------
__device__ float g_w1[768*256];   // packed [q_w*scale ; kv_w]
__device__ float g_b1[768];       // packed [q_b*scale ; kv_b]
__device__ float g_pe[TAB_*H_];   // pe_table [TAB, H]
__device__ float g_xln[NTOK*C_];  // LN1(feat) and reused for LN2 output? (kept separate below)
__device__ float g_q[NTOK*C_];
__device__ float g_k[NTOK*C_];
__device__ float g_v[NTOK*C_];
__device__ float g_ao[NTOK*C_];   // attention output (pre-proj)
__device__ float g_x[NTOK*C_];    // post-attention residual
__device__ float g_xln2[NTOK*C_];
__device__ float g_h1[NTOK*HID_]; // fc1+gelu output

// ---------------- prep: pack W1/b1, compute pe_table -------------------------
__global__ void prep_kernel(const float* __restrict__ qw, const float* __restrict__ qb,
                            const float* __restrict__ kvw, const float* __restrict__ kvb,
                            const float* __restrict__ pre, const float* __restrict__ pew,
                            const float* __restrict__ peb)
{
    const float scale = 0.17677669529663687f; // 32^-0.5
    int t = blockIdx.x * blockDim.x + threadIdx.x;
    if (t < 256*256)        g_w1[t] = qw[t] * scale;
    else if (t < 768*256)   g_w1[t] = kvw[t - 256*256];
    if (t < 256)            g_b1[t] = qb[t] * scale;
    else if (t < 768)       g_b1[t] = kvb[t - 256];
    if (t < TAB_*H_) {
        int tab = t >> 3, h = t & 7;
        float s = peb[h];
        #pragma unroll
        for (int f = 0; f < 5; f++) s += pre[tab*5 + f] * pew[h*5 + f];
        g_pe[t] = s;
    }
}

// ---------------- LayerNorm: one warp per token -------------------------------
// WHICH=0: in = feat (param), out = g_xln.  WHICH=1: in = g_x, out = g_xln2.
template<int WHICH>
__global__ void ln_kernel(const float* __restrict__ xin,
                          const float* __restrict__ w, const float* __restrict__ b)
{
    int gw   = (blockIdx.x * blockDim.x + threadIdx.x) >> 5;
    int lane = threadIdx.x & 31;
    if (gw >= NTOK) return;
    const float* src = (WHICH == 0) ? xin : g_x;
    float*       dst = (WHICH == 0) ? g_xln : g_xln2;
    const float4* xr = (const float4*)(src + (size_t)gw * C_);
    float4 a = xr[lane*2], c = xr[lane*2 + 1];
    float s  = a.x + a.y + a.z + a.w + c.x + c.y + c.z + c.w;
    float ss = a.x*a.x + a.y*a.y + a.z*a.z + a.w*a.w
             + c.x*c.x + c.y*c.y + c.z*c.z + c.w*c.w;
    #pragma unroll
    for (int o = 16; o > 0; o >>= 1) {
        s  += __shfl_xor_sync(0xffffffffu, s,  o);
        ss += __shfl_xor_sync(0xffffffffu, ss, o);
    }
    float mean = s * (1.0f/256.0f);
    float var  = ss * (1.0f/256.0f) - mean*mean;
    float rstd = rsqrtf(var + 1e-5f);
    int c0 = lane * 8;
    float4 w0 = *(const float4*)(w + c0), w1 = *(const float4*)(w + c0 + 4);
    float4 b0 = *(const float4*)(b + c0), b1 = *(const float4*)(b + c0 + 4);
    float4 o0, o1;
    o0.x = (a.x-mean)*rstd*w0.x + b0.x;  o0.y = (a.y-mean)*rstd*w0.y + b0.y;
    o0.z = (a.z-mean)*rstd*w0.z + b0.z;  o0.w = (a.w-mean)*rstd*w0.w + b0.w;
    o1.x = (c.x-mean)*rstd*w1.x + b1.x;  o1.y = (c.y-mean)*rstd*w1.y + b1.y;
    o1.z = (c.z-mean)*rstd*w1.z + b1.z;  o1.w = (c.w-mean)*rstd*w1.w + b1.w;
    float4* yr = (float4*)(dst + (size_t)gw * C_);
    yr[lane*2] = o0; yr[lane*2 + 1] = o1;
}

// ---------------- SGEMM (NT): C[M,N] = A[M,K] @ W[N,K]^T + epilogue ----------
// MODE 0: QKV   A=g_xln,  W=g_w1,   bias=g_b1, scatter -> g_q/g_k/g_v
// MODE 1: proj  A=g_ao,   W=param,  bias=param, +res(feat param) -> g_x
// MODE 2: fc1   A=g_xln2, W=param,  bias=param, gelu -> g_h1
// MODE 3: fc2   A=g_h1,   W=param,  bias=param, +res(g_x) -> out param
#define BM 128
#define BN 128
#define BKK 16

__device__ __forceinline__ float gelu_exact(float v)
{
    return 0.5f * v * (1.0f + erff(v * 0.70710678118654752f));
}

template<int MODE>
__global__ void __launch_bounds__(256) sgemm_nt(const float* __restrict__ Wp,
                                                const float* __restrict__ biasp,
                                                const float* __restrict__ resp,
                                                float* __restrict__ outp,
                                                int Nw, int K)
{
    const float* A  = (MODE == 0) ? g_xln : (MODE == 1) ? g_ao : (MODE == 2) ? g_xln2 : g_h1;
    const float* Wm = (MODE == 0) ? g_w1 : Wp;
    const float* bi = (MODE == 0) ? g_b1 : biasp;

    __shared__ float As[BKK][BM + 4];
    __shared__ float Bs[BKK][BN + 4];

    int bx = blockIdx.x, by = blockIdx.y;
    int tid = threadIdx.x;
    int tx = tid & 15, ty = tid >> 4;

    const float* Ab = A  + (size_t)by * BM * K;
    const float* Bb = Wm + (size_t)bx * BN * K;

    float acc[8][8];
    #pragma unroll
    for (int i = 0; i < 8; i++)
        #pragma unroll
        for (int j = 0; j < 8; j++) acc[i][j] = 0.0f;

    for (int k0 = 0; k0 < K; k0 += BKK) {
        #pragma unroll
        for (int it = 0; it < 2; it++) {
            int v   = tid + it * 256;     // 0..511
            int row = v >> 2;             // 0..127
            int kq  = (v & 3) * 4;        // 0,4,8,12
            float4 av = *(const float4*)(Ab + (size_t)row * K + k0 + kq);
            As[kq+0][row] = av.x; As[kq+1][row] = av.y;
            As[kq+2][row] = av.z; As[kq+3][row] = av.w;
            float4 bv = *(const float4*)(Bb + (size_t)row * K + k0 + kq);
            Bs[kq+0][row] = bv.x; Bs[kq+1][row] = bv.y;
            Bs[kq+2][row] = bv.z; Bs[kq+3][row] = bv.w;
        }
        __syncthreads();
        #pragma unroll
        for (int k = 0; k < BKK; k++) {
            float4 a0 = *(const float4*)&As[k][ty*8];
            float4 a1 = *(const float4*)&As[k][ty*8 + 4];
            float4 b0 = *(const float4*)&Bs[k][tx*8];
            float4 b1 = *(const float4*)&Bs[k][tx*8 + 4];
            float ar[8] = {a0.x,a0.y,a0.z,a0.w,a1.x,a1.y,a1.z,a1.w};
            float br[8] = {b0.x,b0.y,b0.z,b0.w,b1.x,b1.y,b1.z,b1.w};
            #pragma unroll
            for (int i = 0; i < 8; i++)
                #pragma unroll
                for (int j = 0; j < 8; j++)
                    acc[i][j] += ar[i] * br[j];
        }
        __syncthreads();
    }

    int rowg = by * BM + ty * 8;
    int colg = bx * BN + tx * 8;

    if (MODE == 0) {
        #pragma unroll
        for (int i = 0; i < 8; i++) {
            int row = rowg + i;
            #pragma unroll
            for (int j = 0; j < 8; j++) {
                int col = colg + j;
                float v = acc[i][j] + bi[col];
                if (col < 256) {
                    g_q[(size_t)row * C_ + col] = v;
                } else {
                    int o = col - 256;
                    int hh = o >> 6, r = o & 63;
                    if (r < 32) g_k[(size_t)row * C_ + hh*32 + r] = v;
                    else        g_v[(size_t)row * C_ + hh*32 + (r - 32)] = v;
                }
            }
        }
    } else {
        float* dst = (MODE == 1) ? g_x : (MODE == 2) ? g_h1 : outp;
        #pragma unroll
        for (int i = 0; i < 8; i++) {
            size_t base = (size_t)(rowg + i) * Nw + colg;
            #pragma unroll
            for (int j = 0; j < 8; j++) {
                float v = acc[i][j] + bi[colg + j];
                if (MODE == 1) v += resp[base + j];
                if (MODE == 2) v = gelu_exact(v);
                if (MODE == 3) v += g_x[base + j];
                dst[base + j] = v;
            }
        }
    }
}

// ---------------- attention: 1 block per token, 1 warp per head ---------------
__global__ void __launch_bounds__(256) attn_kernel(const int* __restrict__ member_idx,
                                                   const int* __restrict__ pe_idx,
                                                   const float* __restrict__ cmask,
                                                   const float* __restrict__ blank_k,
                                                   const float* __restrict__ blank_v)
{
    int tok  = blockIdx.x;            // 0..16383
    int tid  = threadIdx.x;
    int h    = tid >> 5;
    int lane = tid & 31;
    int b    = tok >> 13;             // N=8192
    int rowbase = b << 13;

    __shared__ int   s_idx[32];
    __shared__ int   s_pe[32];
    __shared__ float s_madd[32];
    if (tid < 32)      s_idx[tid]      = member_idx[(size_t)tok*32 + tid];
    else if (tid < 64) s_pe[tid - 32]  = pe_idx[(size_t)tok*32 + (tid - 32)];
    else if (tid < 96) s_madd[tid - 64] = (1.0f - cmask[(size_t)tok*32 + (tid - 64)]) * -100.0f;
    __syncthreads();

    size_t qoff = (size_t)tok * C_ + h*CH_ + lane;
    float qv = g_q[qoff];

    float vreg[32];
    float myscore = 0.0f;
    #pragma unroll
    for (int m = 0; m < 32; m++) {
        size_t roff = ((size_t)(rowbase + s_idx[m])) * C_ + h*CH_ + lane;
        float kv = g_k[roff];
        vreg[m]  = g_v[roff];
        float d = qv * kv;
        #pragma unroll
        for (int o = 16; o > 0; o >>= 1) d += __shfl_xor_sync(0xffffffffu, d, o);
        if (m == lane) myscore = d;
    }

    myscore += g_pe[s_pe[lane]*H_ + h] + s_madd[lane];

    // blank logit
    float bd = qv * blank_k[h*CH_ + lane];
    #pragma unroll
    for (int o = 16; o > 0; o >>= 1) bd += __shfl_xor_sync(0xffffffffu, bd, o);
    bd = fminf(fmaxf(bd, -5.0f), 5.0f);

    // softmax over 32 members + blank
    float mx = myscore;
    #pragma unroll
    for (int o = 16; o > 0; o >>= 1) mx = fmaxf(mx, __shfl_xor_sync(0xffffffffu, mx, o));
    mx = fmaxf(mx, bd);
    float p  = expf(myscore - mx);
    float pb = expf(bd - mx);
    float ps = p;
    #pragma unroll
    for (int o = 16; o > 0; o >>= 1) ps += __shfl_xor_sync(0xffffffffu, ps, o);
    ps += pb;
    float inv = 1.0f / ps;
    p *= inv;

    float accv = (pb * inv) * blank_v[h*CH_ + lane];
    #pragma unroll
    for (int m = 0; m < 32; m++) {
        float pm = __shfl_sync(0xffffffffu, p, m);
        accv += pm * vreg[m];
    }
    g_ao[qoff] = accv;
}

// ---------------- launch ------------------------------------------------------
extern "C" void kernel_launch(void* const* d_in, const int* in_sizes, int n_in,
                              void* d_out, int out_size)
{
    const float* feat  = (const float*)d_in[0];
    const int*   midx  = (const int*)  d_in[1];
    const float* cmask = (const float*)d_in[2];
    const int*   peidx = (const int*)  d_in[3];
    // d_in[4] = global_attn (unused, always 0)
    const float* pre   = (const float*)d_in[5];
    const float* n1w   = (const float*)d_in[6];
    const float* n1b   = (const float*)d_in[7];
    const float* qw    = (const float*)d_in[8];
    const float* qb    = (const float*)d_in[9];
    const float* kvw   = (const float*)d_in[10];
    const float* kvb   = (const float*)d_in[11];
    const float* bk    = (const float*)d_in[12];
    const float* bv    = (const float*)d_in[13];
    const float* pew   = (const float*)d_in[14];
    const float* peb   = (const float*)d_in[15];
    const float* pjw   = (const float*)d_in[16];
    const float* pjb   = (const float*)d_in[17];
    const float* n2w   = (const float*)d_in[18];
    const float* n2b   = (const float*)d_in[19];
    const float* f1w   = (const float*)d_in[20];
    const float* f1b   = (const float*)d_in[21];
    const float* f2w   = (const float*)d_in[22];
    const float* f2b   = (const float*)d_in[23];
    float* out = (float*)d_out;

    // prep: pack W1/b1 + pe_table
    prep_kernel<<<768, 256>>>(qw, qb, kvw, kvb, pre, pew, peb);

    // LN1: feat -> g_xln
    ln_kernel<0><<<(NTOK*32)/256, 256>>>(feat, n1w, n1b);

    // QKV: g_xln @ g_w1^T -> g_q/g_k/g_v  (M=16384, N=768, K=256)
    sgemm_nt<0><<<dim3(768/BN, NTOK/BM), 256>>>(nullptr, nullptr, nullptr, nullptr, 768, 256);

    // attention -> g_ao
    attn_kernel<<<NTOK, 256>>>(midx, peidx, cmask, bk, bv);

    // proj + residual(feat) -> g_x  (N=256, K=256)
    sgemm_nt<1><<<dim3(256/BN, NTOK/BM), 256>>>(pjw, pjb, feat, nullptr, 256, 256);

    // LN2: g_x -> g_xln2
    ln_kernel<1><<<(NTOK*32)/256, 256>>>(nullptr, n2w, n2b);

    // fc1 + gelu -> g_h1  (N=512, K=256)
    sgemm_nt<2><<<dim3(512/BN, NTOK/BM), 256>>>(f1w, f1b, nullptr, nullptr, 512, 256);

    // fc2 + residual(g_x) -> out  (N=256, K=512)
    sgemm_nt<3><<<dim3(256/BN, NTOK/BM), 256>>>(f2w, f2b, nullptr, out, 256, 512);
}